// round 1
// baseline (speedup 1.0000x reference)
#include <cuda_runtime.h>
#include <cuda_bf16.h>

typedef unsigned long long ull;

#define PW   768      // padded width/height
#define PAD  128      // border
#define IMGW 512
#define MAGIC 8388608.0f   // 2^23

// Padded pair image: g_pair[y][x] = ( I[y-PAD][x-PAD], I[y-PAD][x-PAD+1] ), zero outside.
__device__ float2 g_pair[PW * PW];

// ---------------- packed f32x2 helpers ----------------
__device__ __forceinline__ ull f2u(float a, float b) {
    ull r; asm("mov.b64 %0, {%1, %2};" : "=l"(r) : "f"(a), "f"(b)); return r;
}
__device__ __forceinline__ void u2f(ull v, float& a, float& b) {
    asm("mov.b64 {%0, %1}, %2;" : "=f"(a), "=f"(b) : "l"(v));
}
__device__ __forceinline__ ull fma2(ull a, ull b, ull c) {
    ull d; asm("fma.rn.f32x2 %0, %1, %2, %3;" : "=l"(d) : "l"(a), "l"(b), "l"(c)); return d;
}
__device__ __forceinline__ ull add2(ull a, ull b) {
    ull d; asm("add.rn.f32x2 %0, %1, %2;" : "=l"(d) : "l"(a), "l"(b)); return d;
}

// ---------------- prep: build padded pair image ----------------
__global__ void prep_kernel(const float* __restrict__ img) {
    int x = blockIdx.x * blockDim.x + threadIdx.x;   // 0..767
    int y = blockIdx.y;                               // 0..767
    int sx = x - PAD, sy = y - PAD;
    float v0 = 0.0f, v1 = 0.0f;
    if (sy >= 0 && sy < IMGW) {
        if (sx >= 0 && sx < IMGW)         v0 = __ldg(&img[sy * IMGW + sx]);
        if (sx + 1 >= 0 && sx + 1 < IMGW) v1 = __ldg(&img[sy * IMGW + sx + 1]);
    }
    g_pair[y * PW + x] = make_float2(v0, v1);
}

// ---------------- main radon kernel ----------------
// Thread = one (angle, detector x). 4 independent y-streams (y, y+128, y+256, y+384).
__global__ void __launch_bounds__(256) radon_kernel(const float* __restrict__ angles,
                                                    float* __restrict__ out) {
    const int x = blockIdx.x * blockDim.x + threadIdx.x;   // 0..511
    const int a = blockIdx.y;

    float ang = __ldg(&angles[a]);
    float s, c;
    sincosf(ang, &s, &c);

    // bx = (2x+1)/512 - 1  (pixel-center normalized coord)
    const float bx = fmaf((float)x, 2.0f / 512.0f, 1.0f / 512.0f - 1.0f);
    // ix_padded(y) = Cx + y*s ; iy_padded(y) = Cy + y*c   (PAD already folded in)
    const float Cx = fmaf(256.0f * c, bx, 383.5f - 255.5f * s);
    const float Cy = fmaf(-256.0f * s, bx, 383.5f - 255.5f * c);

    const ull S2   = f2u(s, c);
    const ull NEG1 = f2u(-1.0f, -1.0f);
    const ull ONE2 = f2u(1.0f, 1.0f);

    ull C0 = f2u(Cx, Cy);
    ull C1 = f2u(fmaf(128.0f, s, Cx), fmaf(128.0f, c, Cy));
    ull C2 = f2u(fmaf(256.0f, s, Cx), fmaf(256.0f, c, Cy));
    ull C3 = f2u(fmaf(384.0f, s, Cx), fmaf(384.0f, c, Cy));

    float acc0 = 0.0f, acc1 = 0.0f, acc2 = 0.0f, acc3 = 0.0f;

    const ull* __restrict__ gp = reinterpret_cast<const ull*>(g_pair);

    ull yf2 = f2u(0.0f, 0.0f);

    #pragma unroll 2
    for (int i = 0; i < 128; i++) {
        #pragma unroll
        for (int k = 0; k < 4; k++) {
            const ull Ck = (k == 0) ? C0 : (k == 1) ? C1 : (k == 2) ? C2 : C3;
            float& acc   = (k == 0) ? acc0 : (k == 1) ? acc1 : (k == 2) ? acc2 : acc3;

            // packed coords (ix, iy)
            ull p = fma2(yf2, S2, Ck);
            float px, py; u2f(p, px, py);

            // magic floor (coords are guaranteed positive: >= ~21)
            float tx = __fadd_rd(px, MAGIC);
            float ty = __fadd_rd(py, MAGIC);
            int x0 = __float_as_int(tx) - 0x4B000000;
            int y0 = __float_as_int(ty) - 0x4B000000;
            float wx = px - (tx - MAGIC);
            float wy = py - (ty - MAGIC);

            int idx = y0 * PW + x0;
            ull vt = __ldg(gp + idx);        // (v00, v01)
            ull vb = __ldg(gp + idx + PW);   // (v10, v11)

            // vertical lerp on both x-taps at once
            ull d2  = fma2(vt, NEG1, vb);        // (v10-v00, v11-v01)
            ull wyy = f2u(wy, wy);
            ull m2  = fma2(wyy, d2, vt);         // (m0, m1)
            float m0, m1; u2f(m2, m0, m1);

            // horizontal lerp + accumulate
            acc = fmaf(wx, m1 - m0, acc + m0);
        }
        yf2 = add2(yf2, ONE2);
    }

    out[a * IMGW + x] = (acc0 + acc1) + (acc2 + acc3);
}

extern "C" void kernel_launch(void* const* d_in, const int* in_sizes, int n_in,
                              void* d_out, int out_size) {
    const float* data   = (const float*)d_in[0];
    const float* angles = (const float*)d_in[1];
    // guard against input-order surprises: data has 262144 elems, angles has few
    if (n_in >= 2 && in_sizes[0] < in_sizes[1]) {
        const float* t = data; data = angles; angles = t;
    }
    int nA = (in_sizes[0] < in_sizes[1]) ? in_sizes[0] : in_sizes[1];

    float* out = (float*)d_out;

    dim3 pgrid(PW / 256, PW);
    prep_kernel<<<pgrid, 256>>>(data);

    dim3 rgrid(IMGW / 256, nA);
    radon_kernel<<<rgrid, 256>>>(angles, out);
}

// round 2
// speedup vs baseline: 1.7493x; 1.7493x over previous
#include <cuda_runtime.h>
#include <cuda_bf16.h>

typedef unsigned long long ull;

#define PW    768      // padded width/height
#define PAD   128      // border
#define IMGW  512
#define A_MAX 1024
#define MAGIC 8388608.0f   // 2^23

// Padded pair images.
// gA[vp*PW + up] = ( Ip(vp, up), Ip(vp, up+1) )   -- x-major pairs (normal)
// gB[up*PW + vp] = ( Ip(vp, up), Ip(vp+1, up) )   -- y-major pairs (transposed)
// where Ip(vp,up) = I[vp-PAD][up-PAD], zero outside.
__device__ float2 g_pairA[PW * PW];
__device__ float2 g_pairB[PW * PW];
__device__ float  g_part[2 * A_MAX * IMGW];

// ---------------- packed f32x2 helpers ----------------
__device__ __forceinline__ ull f2u(float a, float b) {
    ull r; asm("mov.b64 %0, {%1, %2};" : "=l"(r) : "f"(a), "f"(b)); return r;
}
__device__ __forceinline__ void u2f(ull v, float& a, float& b) {
    asm("mov.b64 {%0, %1}, %2;" : "=f"(a), "=f"(b) : "l"(v));
}
__device__ __forceinline__ ull fma2(ull a, ull b, ull c) {
    ull d; asm("fma.rn.f32x2 %0, %1, %2, %3;" : "=l"(d) : "l"(a), "l"(b), "l"(c)); return d;
}
__device__ __forceinline__ ull add2(ull a, ull b) {
    ull d; asm("add.rn.f32x2 %0, %1, %2;" : "=l"(d) : "l"(a), "l"(b)); return d;
}

// ---------------- prep A: x-major pair image ----------------
__global__ void prepA_kernel(const float* __restrict__ img) {
    int x = blockIdx.x * blockDim.x + threadIdx.x;   // up: 0..767
    int y = blockIdx.y;                               // vp: 0..767
    int sx = x - PAD, sy = y - PAD;
    float v0 = 0.0f, v1 = 0.0f;
    if (sy >= 0 && sy < IMGW) {
        if (sx >= 0 && sx < IMGW)         v0 = __ldg(&img[sy * IMGW + sx]);
        if (sx + 1 >= 0 && sx + 1 < IMGW) v1 = __ldg(&img[sy * IMGW + sx + 1]);
    }
    g_pairA[y * PW + x] = make_float2(v0, v1);
}

// ---------------- prep B: y-major pair image (smem tile transpose) ----------------
__global__ void prepB_kernel(const float* __restrict__ img) {
    __shared__ float S[33][33];   // S[j][i] = Ip(c0+j, r0+i), padded vs bank conflicts
    const int r0 = blockIdx.x * 32;   // up tile origin
    const int c0 = blockIdx.y * 32;   // vp tile origin
    const int tx = threadIdx.x;       // 0..31
    const int ty = threadIdx.y;       // 0..7

    for (int jj = ty; jj < 33; jj += 8) {
        int vp = c0 + jj, up = r0 + tx;
        int sv = vp - PAD, su = up - PAD;
        float v = 0.0f;
        if (sv >= 0 && sv < IMGW && su >= 0 && su < IMGW)
            v = __ldg(&img[sv * IMGW + su]);
        S[jj][tx] = v;
    }
    __syncthreads();

    for (int ii = ty; ii < 32; ii += 8) {
        // gB[(r0+ii)*PW + (c0+tx)] = (Ip(c0+tx, r0+ii), Ip(c0+tx+1, r0+ii))
        g_pairB[(r0 + ii) * PW + (c0 + tx)] = make_float2(S[tx][ii], S[tx + 1][ii]);
    }
}

// ---------------- main radon kernel ----------------
// blockIdx: (x-chunk, angle, y-half). Each thread: 4 streams of 64 y-samples.
__global__ void __launch_bounds__(256) radon_kernel(const float* __restrict__ angles) {
    const int x = blockIdx.x * blockDim.x + threadIdx.x;   // 0..511
    const int a = blockIdx.y;
    const int h = blockIdx.z;                               // 0 or 1

    float ang = __ldg(&angles[a]);
    float s, c;
    sincosf(ang, &s, &c);

    // bx = (2x+1)/512 - 1
    const float bx = fmaf((float)x, 2.0f / 512.0f, 1.0f / 512.0f - 1.0f);
    // padded sample coords: px(y) = Cx + y*s ; py(y) = Cy + y*c
    const float Cx = fmaf(256.0f * c, bx, 383.5f - 255.5f * s);
    const float Cy = fmaf(-256.0f * s, bx, 383.5f - 255.5f * c);

    // Layout selection: pick the image whose contiguous dim has the larger
    // lane-delta (lane-delta of px is c, of py is -s). Uniform per block.
    const bool tr = fabsf(s) > fabsf(c);
    const float sc0 = tr ? c : s;     // step of first (col) coord
    const float sc1 = tr ? s : c;     // step of second (row) coord
    const float Ca  = tr ? Cy : Cx;   // first (col) base
    const float Cb  = tr ? Cx : Cy;   // second (row) base
    const ull* __restrict__ gp =
        reinterpret_cast<const ull*>(tr ? g_pairB : g_pairA);

    const ull S2   = f2u(sc0, sc1);
    const ull NEG1 = f2u(-1.0f, -1.0f);
    const ull ONE2 = f2u(1.0f, 1.0f);

    const float yb = (float)(h * 256);
    ull C0 = f2u(fmaf(yb +   0.0f, sc0, Ca), fmaf(yb +   0.0f, sc1, Cb));
    ull C1 = f2u(fmaf(yb +  64.0f, sc0, Ca), fmaf(yb +  64.0f, sc1, Cb));
    ull C2 = f2u(fmaf(yb + 128.0f, sc0, Ca), fmaf(yb + 128.0f, sc1, Cb));
    ull C3 = f2u(fmaf(yb + 192.0f, sc0, Ca), fmaf(yb + 192.0f, sc1, Cb));

    float acc0 = 0.0f, acc1 = 0.0f, acc2 = 0.0f, acc3 = 0.0f;

    ull yf2 = f2u(0.0f, 0.0f);

    #pragma unroll 2
    for (int i = 0; i < 64; i++) {
        #pragma unroll
        for (int k = 0; k < 4; k++) {
            const ull Ck = (k == 0) ? C0 : (k == 1) ? C1 : (k == 2) ? C2 : C3;
            float& acc   = (k == 0) ? acc0 : (k == 1) ? acc1 : (k == 2) ? acc2 : acc3;

            // packed coords (col, row) in padded space
            ull p = fma2(yf2, S2, Ck);
            float pc, pr; u2f(p, pc, pr);

            // magic floor (coords guaranteed ~[22, 745], always positive)
            float tc = __fadd_rd(pc, MAGIC);
            float tr_ = __fadd_rd(pr, MAGIC);
            int c0i = __float_as_int(tc) - 0x4B000000;
            int r0i = __float_as_int(tr_) - 0x4B000000;
            float wc = pc - (tc - MAGIC);
            float wr = pr - (tr_ - MAGIC);

            int idx = r0i * PW + c0i;
            ull vt = __ldg(gp + idx);        // pair at (row, col), (row, col+?) packed
            ull vb = __ldg(gp + idx + PW);   // pair one row down

            // lerp along the row direction on both packed taps
            ull d2  = fma2(vt, NEG1, vb);
            ull wrr = f2u(wr, wr);
            ull m2  = fma2(wrr, d2, vt);
            float m0, m1; u2f(m2, m0, m1);

            // lerp along the packed (col) direction + accumulate
            acc = fmaf(wc, m1 - m0, acc + m0);
        }
        yf2 = add2(yf2, ONE2);
    }

    g_part[h * (A_MAX * IMGW) + a * IMGW + x] = (acc0 + acc1) + (acc2 + acc3);
}

// ---------------- reduce halves ----------------
__global__ void reduce_kernel(float* __restrict__ out, int n) {
    int i = blockIdx.x * blockDim.x + threadIdx.x;
    if (i < n)
        out[i] = g_part[i % (A_MAX * IMGW) + (i / (A_MAX * IMGW))] // keep simple: n <= A_MAX*IMGW
               ,
        out[i] = g_part[i] + g_part[A_MAX * IMGW + i];
}

extern "C" void kernel_launch(void* const* d_in, const int* in_sizes, int n_in,
                              void* d_out, int out_size) {
    const float* data   = (const float*)d_in[0];
    const float* angles = (const float*)d_in[1];
    if (n_in >= 2 && in_sizes[0] < in_sizes[1]) {
        const float* t = data; data = angles; angles = t;
    }
    int nA = (in_sizes[0] < in_sizes[1]) ? in_sizes[0] : in_sizes[1];

    float* out = (float*)d_out;

    dim3 pgrid(PW / 256, PW);
    prepA_kernel<<<pgrid, 256>>>(data);

    dim3 bgrid(PW / 32, PW / 32);
    prepB_kernel<<<bgrid, dim3(32, 8)>>>(data);

    dim3 rgrid(IMGW / 256, nA, 2);
    radon_kernel<<<rgrid, 256>>>(angles);

    int n = nA * IMGW;
    reduce_kernel<<<(n + 255) / 256, 256>>>(out, n);
}

// round 3
// speedup vs baseline: 3.2486x; 1.8571x over previous
#include <cuda_runtime.h>
#include <cuda_bf16.h>

typedef unsigned long long ull;

#define PW    768      // padded width/height
#define PAD   128      // border
#define IMGW  512
#define MAGIC 8388608.0f   // 2^23

// Quad images: each texel holds the full 2x2 bilinear stencil.
// A (normal):     QA[r][c] = ( Ip(r,c),  Ip(r,c+1),  Ip(r+1,c),  Ip(r+1,c+1) )
//                 with (r,c) = (image y, image x) in padded space.
// B (transposed): QB[r][c] = ( Tp(r,c),  Tp(r,c+1),  Tp(r+1,c),  Tp(r+1,c+1) )
//                 with Tp(r,c) = Ip(c,r)  (rows = image x, cols = image y).
// Ip(v,u) = I[v-PAD][u-PAD], zero outside.
__device__ float4 g_quadA[PW * PW];
__device__ float4 g_quadB[PW * PW];

// ---------------- packed f32x2 helpers ----------------
__device__ __forceinline__ ull f2u(float a, float b) {
    ull r; asm("mov.b64 %0, {%1, %2};" : "=l"(r) : "f"(a), "f"(b)); return r;
}
__device__ __forceinline__ void u2f(ull v, float& a, float& b) {
    asm("mov.b64 {%0, %1}, %2;" : "=f"(a), "=f"(b) : "l"(v));
}
__device__ __forceinline__ ull fma2(ull a, ull b, ull c) {
    ull d; asm("fma.rn.f32x2 %0, %1, %2, %3;" : "=l"(d) : "l"(a), "l"(b), "l"(c)); return d;
}
__device__ __forceinline__ ull add2(ull a, ull b) {
    ull d; asm("add.rn.f32x2 %0, %1, %2;" : "=l"(d) : "l"(a), "l"(b)); return d;
}
__device__ __forceinline__ void ldg128(const ulonglong2* p, ull& lo, ull& hi) {
    asm("ld.global.nc.v2.u64 {%0, %1}, [%2];" : "=l"(lo), "=l"(hi) : "l"(p));
}

// ---------------- prep A: quad image, normal orientation ----------------
__device__ __forceinline__ float ipad(const float* img, int v, int u) {
    int sv = v - PAD, su = u - PAD;
    if (sv < 0 || sv >= IMGW || su < 0 || su >= IMGW) return 0.0f;
    return __ldg(&img[sv * IMGW + su]);
}

__global__ void prepQA_kernel(const float* __restrict__ img) {
    int c = blockIdx.x * blockDim.x + threadIdx.x;   // 0..767
    int r = blockIdx.y;
    float v00 = ipad(img, r,     c);
    float v01 = ipad(img, r,     c + 1);
    float v10 = ipad(img, r + 1, c);
    float v11 = ipad(img, r + 1, c + 1);
    g_quadA[r * PW + c] = make_float4(v00, v01, v10, v11);
}

// ---------------- prep B: quad image, transposed (smem tile) ----------------
__global__ void prepQB_kernel(const float* __restrict__ img) {
    // Tp(r,c) = Ip(c,r). Tile: r in [r0,r0+32), c in [c0,c0+32).
    // Need Ip(c0..c0+32, r0..r0+32)  ->  S[j][i] = Ip(c0+j, r0+i), 33x33.
    __shared__ float S[33][34];
    const int r0 = blockIdx.x * 32;
    const int c0 = blockIdx.y * 32;
    const int tx = threadIdx.x;   // 0..31
    const int ty = threadIdx.y;   // 0..7

    for (int jj = ty; jj < 33; jj += 8) {
        for (int ii = tx; ii < 33; ii += 32) {
            S[jj][ii] = ipad(img, c0 + jj, r0 + ii);
        }
    }
    __syncthreads();

    for (int ii = ty; ii < 32; ii += 8) {
        // QB[(r0+ii)][(c0+tx)] = (Tp(r,c), Tp(r,c+1), Tp(r+1,c), Tp(r+1,c+1))
        //                      = (S[tx][ii], S[tx+1][ii], S[tx][ii+1], S[tx+1][ii+1])
        g_quadB[(r0 + ii) * PW + (c0 + tx)] =
            make_float4(S[tx][ii], S[tx + 1][ii], S[tx][ii + 1], S[tx + 1][ii + 1]);
    }
}

// ---------------- main radon kernel ----------------
// Warp = 8 detectors x 4 y-lanes (2D patch -> compact L1 footprint).
// Thread: 4 streams x 32 samples, y = yi + 4*t + 128*k.
__global__ void __launch_bounds__(128) radon_kernel(const float* __restrict__ angles,
                                                    float* __restrict__ out) {
    const int lane = threadIdx.x & 31;
    const int warp = threadIdx.x >> 5;
    const int xi   = lane & 7;
    const int yi   = lane >> 3;                     // 0..3
    const int x    = blockIdx.x * 32 + warp * 8 + xi;
    const int a    = blockIdx.y;

    float s, c;
    sincosf(__ldg(&angles[a]), &s, &c);

    // bx = (2x+1)/512 - 1 ; padded coords: px(y)=Cx+y*s, py(y)=Cy+y*c
    const float bx = fmaf((float)x, 2.0f / 512.0f, 1.0f / 512.0f - 1.0f);
    const float Cx = fmaf(256.0f * c, bx, 383.5f - 255.5f * s);
    const float Cy = fmaf(-256.0f * s, bx, 383.5f - 255.5f * c);

    // Layout selection (minimizes rows touched per warp patch).
    const bool  tr   = fabsf(s) > fabsf(c);
    const float dcol = tr ? c : s;      // col-coord step per y
    const float drow = tr ? s : c;      // row-coord step per y
    const float Ca   = tr ? Cy : Cx;
    const float Cb   = tr ? Cx : Cy;
    const ulonglong2* __restrict__ gp =
        reinterpret_cast<const ulonglong2*>(tr ? g_quadB : g_quadA);

    const ull S4   = f2u(4.0f * dcol, 4.0f * drow);  // step per loop iter
    const ull NEG1 = f2u(-1.0f, -1.0f);
    const ull ONE2 = f2u(1.0f, 1.0f);

    const float y0 = (float)yi;
    ull C0 = f2u(fmaf(y0 +   0.0f, dcol, Ca), fmaf(y0 +   0.0f, drow, Cb));
    ull C1 = f2u(fmaf(y0 + 128.0f, dcol, Ca), fmaf(y0 + 128.0f, drow, Cb));
    ull C2 = f2u(fmaf(y0 + 256.0f, dcol, Ca), fmaf(y0 + 256.0f, drow, Cb));
    ull C3 = f2u(fmaf(y0 + 384.0f, dcol, Ca), fmaf(y0 + 384.0f, drow, Cb));

    float acc0 = 0.0f, acc1 = 0.0f, acc2 = 0.0f, acc3 = 0.0f;

    ull t2 = f2u(0.0f, 0.0f);

    #pragma unroll 2
    for (int i = 0; i < 32; i++) {
        #pragma unroll
        for (int k = 0; k < 4; k++) {
            const ull Ck = (k == 0) ? C0 : (k == 1) ? C1 : (k == 2) ? C2 : C3;
            float& acc   = (k == 0) ? acc0 : (k == 1) ? acc1 : (k == 2) ? acc2 : acc3;

            // packed coords (col, row) in padded space
            ull p = fma2(t2, S4, Ck);
            float pc, pr; u2f(p, pc, pr);

            // magic floor (coords guaranteed in ~[21.4, 745.6], positive)
            float tc  = __fadd_rd(pc, MAGIC);
            float trm = __fadd_rd(pr, MAGIC);
            int c0i = __float_as_int(tc)  - 0x4B000000;
            int r0i = __float_as_int(trm) - 0x4B000000;
            float wc = pc - (tc  - MAGIC);
            float wr = pr - (trm - MAGIC);

            int idx = r0i * PW + c0i;
            ull vt, vb;                        // (q00,q01), (q10,q11)
            ldg128(gp + idx, vt, vb);

            // row lerp on both col taps at once
            ull d2  = fma2(vt, NEG1, vb);
            ull wrr = f2u(wr, wr);
            ull m2  = fma2(wrr, d2, vt);
            float m0, m1; u2f(m2, m0, m1);

            // col lerp + accumulate
            acc = fmaf(wc, m1 - m0, acc + m0);
        }
        t2 = add2(t2, ONE2);
    }

    float v = (acc0 + acc1) + (acc2 + acc3);
    // sum over the 4 y-lanes sharing this detector
    v += __shfl_xor_sync(0xFFFFFFFFu, v, 8);
    v += __shfl_xor_sync(0xFFFFFFFFu, v, 16);
    if (yi == 0)
        out[a * IMGW + x] = v;
}

extern "C" void kernel_launch(void* const* d_in, const int* in_sizes, int n_in,
                              void* d_out, int out_size) {
    const float* data   = (const float*)d_in[0];
    const float* angles = (const float*)d_in[1];
    if (n_in >= 2 && in_sizes[0] < in_sizes[1]) {
        const float* t = data; data = angles; angles = t;
    }
    int nA = (in_sizes[0] < in_sizes[1]) ? in_sizes[0] : in_sizes[1];

    float* out = (float*)d_out;

    dim3 agrid(PW / 256, PW);
    prepQA_kernel<<<agrid, 256>>>(data);

    dim3 bgrid(PW / 32, PW / 32);
    prepQB_kernel<<<bgrid, dim3(32, 8)>>>(data);

    dim3 rgrid(IMGW / 32, nA);
    radon_kernel<<<rgrid, 128>>>(angles, out);
}

// round 4
// speedup vs baseline: 4.3319x; 1.3335x over previous
#include <cuda_runtime.h>
#include <cuda_fp16.h>

typedef unsigned long long ull;

#define PW    768      // padded width/height
#define PAD   128      // border
#define IMGW  512
#define MAGIC 8388608.0f   // 2^23

// fp16 quad images: each 8B texel = full 2x2 bilinear stencil (v00,v01,v10,v11).
// A (normal):     rows = image y, cols = image x (padded space)
// B (transposed): rows = image x, cols = image y
__device__ ull g_quadA[PW * PW];
__device__ ull g_quadB[PW * PW];

// ---------------- packed f32x2 helpers ----------------
__device__ __forceinline__ ull f2u(float a, float b) {
    ull r; asm("mov.b64 %0, {%1, %2};" : "=l"(r) : "f"(a), "f"(b)); return r;
}
__device__ __forceinline__ void u2f(ull v, float& a, float& b) {
    asm("mov.b64 {%0, %1}, %2;" : "=f"(a), "=f"(b) : "l"(v));
}
__device__ __forceinline__ ull fma2(ull a, ull b, ull c) {
    ull d; asm("fma.rn.f32x2 %0, %1, %2, %3;" : "=l"(d) : "l"(a), "l"(b), "l"(c)); return d;
}
__device__ __forceinline__ ull add2(ull a, ull b) {
    ull d; asm("add.rn.f32x2 %0, %1, %2;" : "=l"(d) : "l"(a), "l"(b)); return d;
}
__device__ __forceinline__ ull pack64(__half2 lo, __half2 hi) {
    unsigned a = *reinterpret_cast<unsigned*>(&lo);
    unsigned b = *reinterpret_cast<unsigned*>(&hi);
    return (ull)a | ((ull)b << 32);
}

__device__ __forceinline__ float ipad(const float* img, int v, int u) {
    int sv = v - PAD, su = u - PAD;
    if (sv < 0 || sv >= IMGW || su < 0 || su >= IMGW) return 0.0f;
    return __ldg(&img[sv * IMGW + su]);
}

// ---------------- fused prep: both fp16 quad images from one smem tile ----------------
__global__ void prep_kernel(const float* __restrict__ img) {
    __shared__ float S[33][34];            // S[j][i] = Ip(r0+j, c0+i)
    const int r0 = blockIdx.x * 32;
    const int c0 = blockIdx.y * 32;
    const int tx = threadIdx.x;            // 0..31
    const int ty = threadIdx.y;            // 0..7

    for (int j = ty; j < 33; j += 8)
        for (int i = tx; i < 33; i += 32)
            S[j][i] = ipad(img, r0 + j, c0 + i);
    __syncthreads();

    for (int j = ty; j < 32; j += 8) {
        // QA[(r0+j)][(c0+tx)] = (Ip(r,c), Ip(r,c+1), Ip(r+1,c), Ip(r+1,c+1))
        __half2 lo = __floats2half2_rn(S[j][tx],     S[j][tx + 1]);
        __half2 hi = __floats2half2_rn(S[j + 1][tx], S[j + 1][tx + 1]);
        g_quadA[(r0 + j) * PW + (c0 + tx)] = pack64(lo, hi);

        // QB[(c0+j)][(r0+tx)] = (Ip(c,r), Ip(c+1,r), Ip(c,r+1), Ip(c+1,r+1))  [transposed]
        __half2 loB = __floats2half2_rn(S[tx][j],     S[tx + 1][j]);
        __half2 hiB = __floats2half2_rn(S[tx][j + 1], S[tx + 1][j + 1]);
        g_quadB[(c0 + j) * PW + (r0 + tx)] = pack64(loB, hiB);
    }
}

// ---------------- main radon kernel ----------------
// Warp = 8 detectors x 4 y-lanes. Thread: 4 streams x 32 samples, y = yi + 4*t + 128*k.
__global__ void __launch_bounds__(128) radon_kernel(const float* __restrict__ angles,
                                                    float* __restrict__ out) {
    const int lane = threadIdx.x & 31;
    const int warp = threadIdx.x >> 5;
    const int xi   = lane & 7;
    const int yi   = lane >> 3;
    const int x    = blockIdx.x * 32 + warp * 8 + xi;
    const int a    = blockIdx.y;

    float s, c;
    sincosf(__ldg(&angles[a]), &s, &c);

    const float bx = fmaf((float)x, 2.0f / 512.0f, 1.0f / 512.0f - 1.0f);
    const float Cx = fmaf(256.0f * c, bx, 383.5f - 255.5f * s);
    const float Cy = fmaf(-256.0f * s, bx, 383.5f - 255.5f * c);

    // layout selection: contiguous (col) dim gets the large per-detector delta
    const bool  tr   = fabsf(s) > fabsf(c);
    const float dcol = tr ? c : s;
    const float drow = tr ? s : c;
    float Ca = (tr ? Cy : Cx) - 0.5f;     // -0.5 bias: round(p-0.5) == floor(p)
    float Cb = (tr ? Cx : Cy) - 0.5f;
    const char* basep = (const char*)(tr ? g_quadB : g_quadA)
                      - 0x4B000000ULL * (ull)(PW * 8 + 8);   // de-bias the magic ints

    const ull S4    = f2u(4.0f * dcol, 4.0f * drow);
    const ull NEG1  = f2u(-1.0f, -1.0f);
    const ull ONE2  = f2u(1.0f, 1.0f);
    const ull MAG2  = f2u(MAGIC, MAGIC);
    const ull NMAG2 = f2u(-MAGIC, -MAGIC);
    const ull HALF2 = f2u(0.5f, 0.5f);

    const float y0 = (float)yi;
    ull C0 = f2u(fmaf(y0 +   0.0f, dcol, Ca), fmaf(y0 +   0.0f, drow, Cb));
    ull C1 = f2u(fmaf(y0 + 128.0f, dcol, Ca), fmaf(y0 + 128.0f, drow, Cb));
    ull C2 = f2u(fmaf(y0 + 256.0f, dcol, Ca), fmaf(y0 + 256.0f, drow, Cb));
    ull C3 = f2u(fmaf(y0 + 384.0f, dcol, Ca), fmaf(y0 + 384.0f, drow, Cb));

    float acc0 = 0.0f, acc1 = 0.0f, acc2 = 0.0f, acc3 = 0.0f;

    ull t2 = f2u(0.0f, 0.0f);

    #pragma unroll 2
    for (int i = 0; i < 32; i++) {
        #pragma unroll
        for (int k = 0; k < 4; k++) {
            const ull Ck = (k == 0) ? C0 : (k == 1) ? C1 : (k == 2) ? C2 : C3;
            float& acc   = (k == 0) ? acc0 : (k == 1) ? acc1 : (k == 2) ? acc2 : acc3;

            // biased packed coords p' = (col,row) - 0.5
            ull p = fma2(t2, S4, Ck);
            // magic floor via round-to-nearest on p' (ties self-correct through w)
            ull t = add2(p, MAG2);                       // 2^23 + floor(col|row)
            ull f = add2(t, NMAG2);                      // (floor col, floor row) as floats
            ull w = add2(fma2(f, NEG1, p), HALF2);       // fractional weights (wc, wr)

            float tcf, trf; u2f(t, tcf, trf);
            const char* ap = basep
                           + (long long)__float_as_int(trf) * (PW * 8)
                           + ((long long)__float_as_int(tcf) << 3);
            uint2 q = __ldg(reinterpret_cast<const uint2*>(ap));
            __half2 ht = *reinterpret_cast<__half2*>(&q.x);   // (v00, v01)
            __half2 hb = *reinterpret_cast<__half2*>(&q.y);   // (v10, v11)

            float wc, wr; u2f(w, wc, wr);
            unsigned wr2u;
            asm("cvt.rn.f16x2.f32 %0, %1, %2;" : "=r"(wr2u) : "f"(wr), "f"(wr));
            __half2 wr2 = *reinterpret_cast<__half2*>(&wr2u);

            __half2 mh = __hfma2(wr2, __hsub2(hb, ht), ht);   // row lerp, both col taps
            float m0 = __low2float(mh), m1 = __high2float(mh);

            acc = fmaf(wc, m1 - m0, acc + m0);                // col lerp + accumulate
        }
        t2 = add2(t2, ONE2);
    }

    float v = (acc0 + acc1) + (acc2 + acc3);
    v += __shfl_xor_sync(0xFFFFFFFFu, v, 8);
    v += __shfl_xor_sync(0xFFFFFFFFu, v, 16);
    if (yi == 0)
        out[a * IMGW + x] = v;
}

extern "C" void kernel_launch(void* const* d_in, const int* in_sizes, int n_in,
                              void* d_out, int out_size) {
    const float* data   = (const float*)d_in[0];
    const float* angles = (const float*)d_in[1];
    if (n_in >= 2 && in_sizes[0] < in_sizes[1]) {
        const float* t = data; data = angles; angles = t;
    }
    int nA = (in_sizes[0] < in_sizes[1]) ? in_sizes[0] : in_sizes[1];

    float* out = (float*)d_out;

    dim3 pgrid(PW / 32, PW / 32);
    prep_kernel<<<pgrid, dim3(32, 8)>>>(data);

    dim3 rgrid(IMGW / 32, nA);
    radon_kernel<<<rgrid, 128>>>(angles, out);
}

// round 5
// speedup vs baseline: 4.5337x; 1.0466x over previous
#include <cuda_runtime.h>
#include <cuda_fp16.h>

typedef unsigned long long ull;

#define PW    768      // padded width/height
#define PAD   128      // border
#define IMGW  512
#define MAGIC 8388608.0f      // 2^23
#define MAGICH 8388607.5f     // 2^23 - 0.5

// fp16 differential quad images: 8B texel = (v00, dx | dy, dxy)
// dx = v01-v00, dy = v10-v00, dxy = v11-v01-v10+v00
// bilinear: val = (v00 + wr*dy) + wc*(dx + wr*dxy)
// A (normal):     rows = image y, cols = image x (padded space)
// B (transposed): rows = image x, cols = image y
__device__ ull g_quadA[PW * PW];
__device__ ull g_quadB[PW * PW];

// ---------------- packed f32x2 helpers ----------------
__device__ __forceinline__ ull f2u(float a, float b) {
    ull r; asm("mov.b64 %0, {%1, %2};" : "=l"(r) : "f"(a), "f"(b)); return r;
}
__device__ __forceinline__ void u2f(ull v, float& a, float& b) {
    asm("mov.b64 {%0, %1}, %2;" : "=f"(a), "=f"(b) : "l"(v));
}
__device__ __forceinline__ ull fma2(ull a, ull b, ull c) {
    ull d; asm("fma.rn.f32x2 %0, %1, %2, %3;" : "=l"(d) : "l"(a), "l"(b), "l"(c)); return d;
}
__device__ __forceinline__ ull add2(ull a, ull b) {
    ull d; asm("add.rn.f32x2 %0, %1, %2;" : "=l"(d) : "l"(a), "l"(b)); return d;
}
__device__ __forceinline__ ull packq(float v00, float v01, float v10, float v11) {
    float dx  = v01 - v00;
    float dy  = v10 - v00;
    float dxy = (v11 - v10) - (v01 - v00);
    __half2 lo = __floats2half2_rn(v00, dx);
    __half2 hi = __floats2half2_rn(dy, dxy);
    unsigned a = *reinterpret_cast<unsigned*>(&lo);
    unsigned b = *reinterpret_cast<unsigned*>(&hi);
    return (ull)a | ((ull)b << 32);
}

__device__ __forceinline__ float ipad(const float* img, int v, int u) {
    int sv = v - PAD, su = u - PAD;
    if (sv < 0 || sv >= IMGW || su < 0 || su >= IMGW) return 0.0f;
    return __ldg(&img[sv * IMGW + su]);
}

// ---------------- fused prep: both differential quad images ----------------
__global__ void prep_kernel(const float* __restrict__ img) {
    __shared__ float S[33][34];            // S[j][i] = Ip(r0+j, c0+i)
    const int r0 = blockIdx.x * 32;
    const int c0 = blockIdx.y * 32;
    const int tx = threadIdx.x;            // 0..31
    const int ty = threadIdx.y;            // 0..7

    for (int j = ty; j < 33; j += 8)
        for (int i = tx; i < 33; i += 32)
            S[j][i] = ipad(img, r0 + j, c0 + i);
    __syncthreads();

    for (int j = ty; j < 32; j += 8) {
        // QA rows = image y: (v00,v01,v10,v11) = S[j][tx], S[j][tx+1], S[j+1][tx], S[j+1][tx+1]
        g_quadA[(r0 + j) * PW + (c0 + tx)] =
            packq(S[j][tx], S[j][tx + 1], S[j + 1][tx], S[j + 1][tx + 1]);
        // QB rows = image x: (v00,v01,v10,v11) = S[tx][j], S[tx+1][j], S[tx][j+1], S[tx+1][j+1]
        g_quadB[(c0 + j) * PW + (r0 + tx)] =
            packq(S[tx][j], S[tx + 1][j], S[tx][j + 1], S[tx + 1][j + 1]);
    }
}

// ---------------- main radon kernel ----------------
// Warp = 8 detectors x 4 y-lanes. Thread: 4 streams x 32 samples, y = yi + 4*t + 128*k.
__global__ void __launch_bounds__(128) radon_kernel(const float* __restrict__ angles,
                                                    float* __restrict__ out) {
    const int lane = threadIdx.x & 31;
    const int warp = threadIdx.x >> 5;
    const int xi   = lane & 7;
    const int yi   = lane >> 3;
    const int x    = blockIdx.x * 32 + warp * 8 + xi;
    const int a    = blockIdx.y;

    float s, c;
    sincosf(__ldg(&angles[a]), &s, &c);

    const float bx = fmaf((float)x, 2.0f / 512.0f, 1.0f / 512.0f - 1.0f);
    const float Cx = fmaf(256.0f * c, bx, 383.5f - 255.5f * s);
    const float Cy = fmaf(-256.0f * s, bx, 383.5f - 255.5f * c);

    // layout selection: contiguous (col) dim gets the large per-detector delta
    const bool  tr   = fabsf(s) > fabsf(c);
    const float dcol = tr ? c : s;
    const float drow = tr ? s : c;
    const float Ca   = tr ? Cy : Cx;      // unbiased: magic constant carries the -0.5
    const float Cb   = tr ? Cx : Cy;
    const char* basep = (const char*)(tr ? g_quadB : g_quadA)
                      - 0x4B000000ULL * (ull)(PW * 8 + 8);   // de-bias the magic ints

    const ull S4    = f2u(4.0f * dcol, 4.0f * drow);
    const ull NEG1  = f2u(-1.0f, -1.0f);
    const ull ONE2  = f2u(1.0f, 1.0f);
    const ull MAGH2 = f2u(MAGICH, MAGICH);    // 2^23 - 0.5: rn(P+MAGH) = MAGIC + floor(P)
    const ull NMAG2 = f2u(-MAGIC, -MAGIC);

    const float y0 = (float)yi;
    ull C0 = f2u(fmaf(y0 +   0.0f, dcol, Ca), fmaf(y0 +   0.0f, drow, Cb));
    ull C1 = f2u(fmaf(y0 + 128.0f, dcol, Ca), fmaf(y0 + 128.0f, drow, Cb));
    ull C2 = f2u(fmaf(y0 + 256.0f, dcol, Ca), fmaf(y0 + 256.0f, drow, Cb));
    ull C3 = f2u(fmaf(y0 + 384.0f, dcol, Ca), fmaf(y0 + 384.0f, drow, Cb));

    float am0 = 0.0f, am1 = 0.0f, am2 = 0.0f, am3 = 0.0f;   // m0 accumulators
    float ad0 = 0.0f, ad1 = 0.0f, ad2 = 0.0f, ad3 = 0.0f;   // wc*md accumulators

    ull t2 = f2u(0.0f, 0.0f);

    #pragma unroll 2
    for (int i = 0; i < 32; i++) {
        #pragma unroll
        for (int k = 0; k < 4; k++) {
            const ull Ck = (k == 0) ? C0 : (k == 1) ? C1 : (k == 2) ? C2 : C3;
            float& am    = (k == 0) ? am0 : (k == 1) ? am1 : (k == 2) ? am2 : am3;
            float& ad    = (k == 0) ? ad0 : (k == 1) ? ad1 : (k == 2) ? ad2 : ad3;

            // packed coords (col, row), unbiased
            ull p = fma2(t2, S4, Ck);
            ull t = add2(p, MAGH2);            // MAGIC + floor(col|row)
            ull f = add2(t, NMAG2);            // (floor col, floor row) exact
            ull w = fma2(f, NEG1, p);          // fractional weights (wc, wr)

            float tcf, trf; u2f(t, tcf, trf);
            const char* ap = basep
                           + (long long)__float_as_int(trf) * (PW * 8)
                           + ((long long)__float_as_int(tcf) << 3);
            uint2 q = __ldg(reinterpret_cast<const uint2*>(ap));
            __half2 A = *reinterpret_cast<__half2*>(&q.x);   // (v00, dx)
            __half2 B = *reinterpret_cast<__half2*>(&q.y);   // (dy, dxy)

            float wc, wr; u2f(w, wc, wr);
            unsigned wr2u;
            asm("cvt.rn.f16x2.f32 %0, %1, %2;" : "=r"(wr2u) : "f"(wr), "f"(wr));
            __half2 wr2 = *reinterpret_cast<__half2*>(&wr2u);

            __half2 mh = __hfma2(wr2, B, A);                 // (m0, md)
            float m0 = __low2float(mh), md = __high2float(mh);

            am += m0;
            ad = fmaf(wc, md, ad);
        }
        t2 = add2(t2, ONE2);
    }

    float v = ((am0 + ad0) + (am1 + ad1)) + ((am2 + ad2) + (am3 + ad3));
    v += __shfl_xor_sync(0xFFFFFFFFu, v, 8);
    v += __shfl_xor_sync(0xFFFFFFFFu, v, 16);
    if (yi == 0)
        out[a * IMGW + x] = v;
}

extern "C" void kernel_launch(void* const* d_in, const int* in_sizes, int n_in,
                              void* d_out, int out_size) {
    const float* data   = (const float*)d_in[0];
    const float* angles = (const float*)d_in[1];
    if (n_in >= 2 && in_sizes[0] < in_sizes[1]) {
        const float* t = data; data = angles; angles = t;
    }
    int nA = (in_sizes[0] < in_sizes[1]) ? in_sizes[0] : in_sizes[1];

    float* out = (float*)d_out;

    dim3 pgrid(PW / 32, PW / 32);
    prep_kernel<<<pgrid, dim3(32, 8)>>>(data);

    dim3 rgrid(IMGW / 32, nA);
    radon_kernel<<<rgrid, 128>>>(angles, out);
}